// round 1
// baseline (speedup 1.0000x reference)
#include <cuda_runtime.h>

#define B_  128
#define N_  512
#define D_  300
#define NC_ 10
#define DC_ 64
#define M_  640   // NC_*DC_

// Scratch (device globals; allocation-free per harness rules)
__device__ __align__(16) float g_y0p[B_*4*D_];    // colsum partials [B][4][D]
__device__ __align__(16) float g_v[B_*NC_*D_];    // v = W_i o_i     [B][NC][D]
__device__ __align__(16) float g_y[B_*NC_*D_];    // y = sum c x     [B][NC][D]

// ---------------------------------------------------------------------------
// Kernel 1: per-batch column sums of x (iteration-0 y is 0.1 * colsum)
// grid (B, 4), 256 threads; block (b,q) sums rows [q*128, q*128+128)
// ---------------------------------------------------------------------------
__global__ void k_colsum(const float* __restrict__ x) {
    const int b = blockIdx.x, q = blockIdx.y;
    const float* xb = x + (size_t)(b*N_ + q*128)*D_;
    for (int d = threadIdx.x; d < D_; d += blockDim.x) {
        float a0=0.f, a1=0.f, a2=0.f, a3=0.f;
        #pragma unroll 4
        for (int r = 0; r < 128; r += 4) {
            a0 += xb[(size_t)(r+0)*D_ + d];
            a1 += xb[(size_t)(r+1)*D_ + d];
            a2 += xb[(size_t)(r+2)*D_ + d];
            a3 += xb[(size_t)(r+3)*D_ + d];
        }
        g_y0p[(b*4 + q)*D_ + d] = (a0+a1)+(a2+a3);
    }
}

// ---------------------------------------------------------------------------
// Kernel 2: capsule-side reduce:  y -> s = W_i^T y -> o = squash(s) -> v = W_i o
// grid (NC, B/4), 128 threads. W_i slice cached in smem (swizzled, conflict-free
// for both row-parallel and col-parallel access).
// phase 0: y from 0.1*colsum partials; writes v
// phase 1: y from g_y;                 writes v
// phase 2: y from g_y;                 writes o to d_out (final output)
// ---------------------------------------------------------------------------
__global__ void k_caps(const float* __restrict__ W, float* __restrict__ out, int phase) {
    extern __shared__ float sm[];
    float* Ws  = sm;               // [D][64] swizzled: Ws[d*64 + ((k+d)&63)]
    float* ys  = Ws + D_*64;       // [304]
    float* ss  = ys + 304;         // [128]
    float* os  = ss + 128;         // [64]
    float* red = os + 64;          // [32]
    const int i   = blockIdx.x;
    const int tid = threadIdx.x;

    for (int idx = tid; idx < D_*64; idx += 128) {
        const int d = idx >> 6, k = idx & 63;
        Ws[(d<<6) + ((k + d) & 63)] = W[(size_t)d*M_ + i*DC_ + k];
    }
    __syncthreads();

    for (int bb = 0; bb < 4; ++bb) {
        const int b = blockIdx.y*4 + bb;
        if (phase == 0) {
            for (int d = tid; d < D_; d += 128) {
                const float* p = g_y0p + (size_t)b*4*D_ + d;
                ys[d] = 0.1f*(p[0] + p[D_] + p[2*D_] + p[3*D_]);
            }
        } else {
            for (int d = tid; d < D_; d += 128)
                ys[d] = g_y[((size_t)b*NC_ + i)*D_ + d];
        }
        __syncthreads();

        // s_k = sum_d W[d][i*64+k] * y[d]; split d into two halves across 128 thr
        const int k = tid & 63, h = tid >> 6;
        float s = 0.f;
        #pragma unroll 5
        for (int d = h*150; d < h*150 + 150; ++d)
            s = fmaf(Ws[(d<<6) + ((k + d) & 63)], ys[d], s);
        ss[tid] = s;
        __syncthreads();

        float sk = 0.f, myq = 0.f;
        if (tid < 64) { sk = ss[tid] + ss[tid + 64]; myq = sk*sk; }
        #pragma unroll
        for (int off = 16; off; off >>= 1) myq += __shfl_xor_sync(0xffffffffu, myq, off);
        if (tid == 0)  red[0] = myq;
        if (tid == 32) red[1] = myq;
        __syncthreads();
        const float rinv = rsqrtf(red[0] + red[1] + 1e-7f);   // squash: x/sqrt(|x|^2+eps)
        if (tid < 64) {
            const float o = sk * rinv;
            os[tid] = o;
            if (phase == 2) out[((size_t)b*NC_ + i)*DC_ + tid] = o;
        }
        __syncthreads();

        if (phase != 2) {
            // v_d = sum_k W[d][i*64+k] * o_k
            for (int d = tid; d < D_; d += 128) {
                float acc = 0.f;
                #pragma unroll 8
                for (int kk = 0; kk < 64; ++kk)
                    acc = fmaf(Ws[(d<<6) + ((kk + d) & 63)], os[kk], acc);
                g_v[((size_t)b*NC_ + i)*D_ + d] = acc;
            }
        }
        __syncthreads();
    }
}

// ---------------------------------------------------------------------------
// Kernel 3: main routing pass (one iteration). grid (B), 256 threads.
// Per row j: t_i = x_j . v_i  -> softmax over i -> y_i += c_i * x_j
// v and y partials live in registers (lane owns d-pairs 2*lane + 64*t).
// ---------------------------------------------------------------------------
__global__ void __launch_bounds__(256, 1) k_main(const float* __restrict__ x) {
    __shared__ __align__(16) float slab[4][NC_][D_];   // 48000 B cross-warp y merge
    const int b    = blockIdx.x;
    const int w    = threadIdx.x >> 5;
    const int lane = threadIdx.x & 31;

    const float* vb = g_v + (size_t)b*NC_*D_;
    float2 vr[NC_][5];
    #pragma unroll
    for (int i = 0; i < NC_; ++i) {
        #pragma unroll
        for (int t = 0; t < 4; ++t)
            vr[i][t] = *(const float2*)(vb + i*D_ + 2*lane + 64*t);
        vr[i][4] = (lane < 22) ? *(const float2*)(vb + i*D_ + 2*lane + 256)
                               : make_float2(0.f, 0.f);
    }
    float2 yr[NC_][5];
    #pragma unroll
    for (int i = 0; i < NC_; ++i)
        #pragma unroll
        for (int t = 0; t < 5; ++t) yr[i][t] = make_float2(0.f, 0.f);

    const float* xb = x + (size_t)b*N_*D_;
    for (int j = w*64; j < w*64 + 64; ++j) {
        const float* xr = xb + (size_t)j*D_;
        float2 xq[5];
        #pragma unroll
        for (int t = 0; t < 4; ++t) xq[t] = *(const float2*)(xr + 2*lane + 64*t);
        xq[4] = (lane < 22) ? *(const float2*)(xr + 2*lane + 256)
                            : make_float2(0.f, 0.f);

        float tl[NC_];
        #pragma unroll
        for (int i = 0; i < NC_; ++i) {
            float ax = 0.f, ay = 0.f;
            #pragma unroll
            for (int t = 0; t < 5; ++t) {
                ax = fmaf(xq[t].x, vr[i][t].x, ax);
                ay = fmaf(xq[t].y, vr[i][t].y, ay);
            }
            tl[i] = ax + ay;
        }
        // butterfly reduce the 10 dots over 32 lanes (all lanes end with full sums)
        #pragma unroll
        for (int i = 0; i < NC_; ++i) {
            #pragma unroll
            for (int off = 16; off; off >>= 1)
                tl[i] += __shfl_xor_sync(0xffffffffu, tl[i], off);
        }
        // softmax over the 10 capsules (|t| <~ 8, no max-sub needed in fp32)
        float se = 0.f;
        #pragma unroll
        for (int i = 0; i < NC_; ++i) { tl[i] = __expf(tl[i]); se += tl[i]; }
        const float rs = __frcp_rn(se);
        #pragma unroll
        for (int i = 0; i < NC_; ++i) {
            const float c = tl[i] * rs;
            #pragma unroll
            for (int t = 0; t < 5; ++t) {
                yr[i][t].x = fmaf(c, xq[t].x, yr[i][t].x);
                yr[i][t].y = fmaf(c, xq[t].y, yr[i][t].y);
            }
        }
    }

    // merge 8 warp partials: warps 0-3 store slabs, warps 4-7 add into them
    if (w < 4) {
        #pragma unroll
        for (int i = 0; i < NC_; ++i)
            #pragma unroll
            for (int t = 0; t < 5; ++t) {
                const int d = 2*lane + 64*t;
                if (d < D_) *(float2*)&slab[w][i][d] = yr[i][t];
            }
    }
    __syncthreads();
    if (w >= 4) {
        #pragma unroll
        for (int i = 0; i < NC_; ++i)
            #pragma unroll
            for (int t = 0; t < 5; ++t) {
                const int d = 2*lane + 64*t;
                if (d < D_) {
                    float2* p = (float2*)&slab[w-4][i][d];
                    float2 v0 = *p;
                    v0.x += yr[i][t].x; v0.y += yr[i][t].y;
                    *p = v0;
                }
            }
    }
    __syncthreads();
    float* yo = g_y + (size_t)b*NC_*D_;
    const float* s0 = &slab[0][0][0];
    const float* s1 = &slab[1][0][0];
    const float* s2 = &slab[2][0][0];
    const float* s3 = &slab[3][0][0];
    for (int idx = threadIdx.x; idx < NC_*D_; idx += 256)
        yo[idx] = (s0[idx] + s1[idx]) + (s2[idx] + s3[idx]);
}

// ---------------------------------------------------------------------------
extern "C" void kernel_launch(void* const* d_in, const int* in_sizes, int n_in,
                              void* d_out, int out_size) {
    const float* x = (const float*)d_in[0];
    const float* W = (const float*)d_in[1];
    if (n_in >= 2 && in_sizes[0] == D_*M_) {    // guard against input-order swap
        x = (const float*)d_in[1];
        W = (const float*)d_in[0];
    }
    float* out = (float*)d_out;

    const int CAPS_SMEM = (D_*64 + 304 + 128 + 64 + 32) * (int)sizeof(float);
    cudaFuncSetAttribute(k_caps, cudaFuncAttributeMaxDynamicSharedMemorySize, CAPS_SMEM);

    // iter 0: c uniform (=0.1) -> y = 0.1*colsum -> o0, v0
    k_colsum<<<dim3(B_, 4), 256>>>(x);
    k_caps<<<dim3(NC_, B_/4), 128, CAPS_SMEM>>>(W, out, 0);
    // iters 1..4: b = x.v -> softmax -> y;  y -> o -> v  (iter 4 writes output)
    for (int it = 1; it <= 4; ++it) {
        k_main<<<B_, 256>>>(x);
        k_caps<<<dim3(NC_, B_/4), 128, CAPS_SMEM>>>(W, out, it == 4 ? 2 : 1);
    }
}

// round 4
// speedup vs baseline: 1.4681x; 1.4681x over previous
#include <cuda_runtime.h>

#define B_  128
#define N_  512
#define D_  300
#define NC_ 10
#define DC_ 64
#define M_  640   // NC_*DC_

// Scratch (device globals; allocation-free per harness rules)
__device__ __align__(16) float g_y0p[B_*4*D_];    // colsum partials [B][4][D]
__device__ __align__(16) float g_v[B_*NC_*D_];    // v = W_i o_i     [B][NC][D]
__device__ __align__(16) float g_y[B_*NC_*D_];    // y = sum c x     [B][NC][D]

// ---- packed f32x2 FMA (PTX-only; ptxas never auto-fuses) -------------------
__device__ __forceinline__ float2 ffma2(float2 a, float2 b, float2 c) {
    float2 d;
    asm("fma.rn.f32x2 %0, %1, %2, %3;"
        : "=l"(*reinterpret_cast<unsigned long long*>(&d))
        : "l"(*reinterpret_cast<const unsigned long long*>(&a)),
          "l"(*reinterpret_cast<const unsigned long long*>(&b)),
          "l"(*reinterpret_cast<const unsigned long long*>(&c)));
    return d;
}
// ---- warp all-lane sum (REDUX.f32 not supported on sm_103 -> butterfly) ----
__device__ __forceinline__ float warp_sum(float v) {
    #pragma unroll
    for (int off = 16; off; off >>= 1) v += __shfl_xor_sync(0xffffffffu, v, off);
    return v;
}

// ---------------------------------------------------------------------------
// Kernel 1: per-batch column sums of x (iteration-0 y is 0.1 * colsum)
// ---------------------------------------------------------------------------
__global__ void k_colsum(const float* __restrict__ x) {
    const int b = blockIdx.x, q = blockIdx.y;
    const float* xb = x + (size_t)(b*N_ + q*128)*D_;
    for (int d = threadIdx.x; d < D_; d += blockDim.x) {
        float a0=0.f, a1=0.f, a2=0.f, a3=0.f;
        #pragma unroll 4
        for (int r = 0; r < 128; r += 4) {
            a0 += xb[(size_t)(r+0)*D_ + d];
            a1 += xb[(size_t)(r+1)*D_ + d];
            a2 += xb[(size_t)(r+2)*D_ + d];
            a3 += xb[(size_t)(r+3)*D_ + d];
        }
        g_y0p[(b*4 + q)*D_ + d] = (a0+a1)+(a2+a3);
    }
}

// ---------------------------------------------------------------------------
// Kernel 2: capsule-side reduce for an 8-batch tile.
//   y -> s = W_i^T y -> o = squash(s) -> v = W_i o
// grid (NC, B/8) = (10,16), 256 threads. W_i slice (300x64) cached in smem,
// swizzled so BOTH k-parallel (S phase) and d-parallel (V phase) access are
// conflict-free. Multiple independent FMA chains per thread throughout.
// phase 0: y from 0.1*colsum; writes v.  phase 1: y from g_y; writes v.
// phase 2: y from g_y; writes o to out (no v).
// ---------------------------------------------------------------------------
__global__ void __launch_bounds__(256) k_caps(const float* __restrict__ W,
                                              float* __restrict__ out, int phase) {
    extern __shared__ float sm[];
    float* Ws = sm;                 // [300][64] swizzled: Ws[d*64 + ((k+d)&63)]
    float* ys = Ws + D_*64;         // [8][304]
    float* ss = ys + 8*304;         // [8][64]
    float* os = ss + 8*64;          // [8][64]
    const int i   = blockIdx.x;
    const int bt  = blockIdx.y*8;   // batch tile base
    const int tid = threadIdx.x;

    // cache W_i (coalesced: 64 consecutive k per d-row)
    for (int idx = tid; idx < D_*64; idx += 256) {
        const int d = idx >> 6, k = idx & 63;
        Ws[(d<<6) + ((k + d) & 63)] = W[(size_t)d*M_ + i*DC_ + k];
    }
    // load y for 8 batches
    if (phase == 0) {
        #pragma unroll
        for (int bb = 0; bb < 8; ++bb)
            for (int d = tid; d < D_; d += 256) {
                const float* p = g_y0p + (size_t)(bt+bb)*4*D_ + d;
                ys[bb*304 + d] = 0.1f*((p[0] + p[D_]) + (p[2*D_] + p[3*D_]));
            }
    } else {
        #pragma unroll
        for (int bb = 0; bb < 8; ++bb)
            for (int d = tid; d < D_; d += 256)
                ys[bb*304 + d] = g_y[((size_t)(bt+bb)*NC_ + i)*D_ + d];
    }
    __syncthreads();

    // S phase: s[b][k] = sum_d Ws[d][k] * y[b][d]; thread (k = tid&63, h = tid>>6)
    // covers b = h and h+4; 4 independent accumulator chains.
    {
        const int k = tid & 63, h = tid >> 6;        // h uniform per warp
        const float* y0 = ys + h*304;
        const float* y1 = ys + (h+4)*304;
        float a0=0.f, a1=0.f, b0=0.f, b1=0.f;
        #pragma unroll 4
        for (int d = 0; d < D_; d += 2) {
            const float w0 = Ws[(d<<6)     + ((k + d)     & 63)];
            const float w1 = Ws[((d+1)<<6) + ((k + d + 1) & 63)];
            a0 = fmaf(w0, y0[d],   a0);
            a1 = fmaf(w0, y1[d],   a1);
            b0 = fmaf(w1, y0[d+1], b0);
            b1 = fmaf(w1, y1[d+1], b1);
        }
        ss[h*64 + k]     = a0 + b0;
        ss[(h+4)*64 + k] = a1 + b1;
    }
    __syncthreads();

    // squash: warp w owns batch bt+w (2 values per lane)
    {
        const int w = tid >> 5, lane = tid & 31;
        const float s0 = ss[w*64 + lane], s1 = ss[w*64 + lane + 32];
        const float q  = warp_sum(fmaf(s0, s0, s1*s1));
        const float ri = rsqrtf(q + 1e-7f);
        const float o0 = s0*ri, o1 = s1*ri;
        os[w*64 + lane]      = o0;
        os[w*64 + lane + 32] = o1;
        if (phase == 2) {
            float* op = out + ((size_t)(bt+w)*NC_ + i)*DC_;
            op[lane]      = o0;
            op[lane + 32] = o1;
        }
    }
    __syncthreads();

    // V phase: v[b][d] = sum_k Ws[d][k] * o[b][k]; 2400 outputs, 2 interleaved
    // chains per thread. Lane-consecutive idx -> consecutive d -> conflict-free.
    if (phase != 2) {
        #pragma unroll
        for (int base = 0; base < 2400; base += 512) {
            const int i0 = base + tid, i1 = i0 + 256;
            const bool h1 = (i1 < 2400);
            const int b0i = i0/300, d0 = i0 - 300*b0i;
            const int b1i = h1 ? i1/300 : 0, d1 = h1 ? i1 - 300*b1i : 0;
            const float* o0 = os + b0i*64;
            const float* o1 = os + b1i*64;
            float a0=0.f, a1=0.f;
            #pragma unroll 8
            for (int kk = 0; kk < 64; ++kk) {
                a0 = fmaf(Ws[(d0<<6) + ((kk + d0) & 63)], o0[kk], a0);
                a1 = fmaf(Ws[(d1<<6) + ((kk + d1) & 63)], o1[kk], a1);
            }
            g_v[((size_t)(bt+b0i)*NC_ + i)*D_ + d0] = a0;
            if (h1) g_v[((size_t)(bt+b1i)*NC_ + i)*D_ + d1] = a1;
        }
    }
}

// ---------------------------------------------------------------------------
// Kernel 3: main routing pass (one iteration). grid (B), 256 threads.
// Per row j: t_i = x_j . v_i  -> softmax over i -> y_i += c_i * x_j
// v and y partials register-resident; packed f32x2 FMA; butterfly warp sums.
// ---------------------------------------------------------------------------
__global__ void __launch_bounds__(256, 1) k_main(const float* __restrict__ x) {
    __shared__ __align__(16) float slab[4][NC_][D_];   // 48000 B cross-warp y merge
    const int b    = blockIdx.x;
    const int w    = threadIdx.x >> 5;
    const int lane = threadIdx.x & 31;

    const float* vb = g_v + (size_t)b*NC_*D_;
    float2 vr[NC_][5];
    #pragma unroll
    for (int i = 0; i < NC_; ++i) {
        #pragma unroll
        for (int t = 0; t < 4; ++t)
            vr[i][t] = *(const float2*)(vb + i*D_ + 2*lane + 64*t);
        vr[i][4] = (lane < 22) ? *(const float2*)(vb + i*D_ + 2*lane + 256)
                               : make_float2(0.f, 0.f);
    }
    float2 yr[NC_][5];
    #pragma unroll
    for (int i = 0; i < NC_; ++i)
        #pragma unroll
        for (int t = 0; t < 5; ++t) yr[i][t] = make_float2(0.f, 0.f);

    const float* xb = x + (size_t)b*N_*D_;
    for (int j = w*64; j < w*64 + 64; ++j) {
        const float* xr = xb + (size_t)j*D_;
        float2 xq[5];
        #pragma unroll
        for (int t = 0; t < 4; ++t) xq[t] = *(const float2*)(xr + 2*lane + 64*t);
        xq[4] = (lane < 22) ? *(const float2*)(xr + 2*lane + 256)
                            : make_float2(0.f, 0.f);

        float tl[NC_];
        #pragma unroll
        for (int i = 0; i < NC_; ++i) {
            float2 acc = make_float2(0.f, 0.f);
            #pragma unroll
            for (int t = 0; t < 5; ++t) acc = ffma2(xq[t], vr[i][t], acc);
            tl[i] = acc.x + acc.y;
        }
        // butterfly reduce the 10 dots over 32 lanes (all lanes get full sums)
        #pragma unroll
        for (int i = 0; i < NC_; ++i) {
            #pragma unroll
            for (int off = 16; off; off >>= 1)
                tl[i] += __shfl_xor_sync(0xffffffffu, tl[i], off);
        }
        // softmax over the 10 capsules (|t| small in fp32; no max-sub needed)
        float se = 0.f;
        #pragma unroll
        for (int i = 0; i < NC_; ++i) { tl[i] = __expf(tl[i]); se += tl[i]; }
        const float rs = __frcp_rn(se);
        #pragma unroll
        for (int i = 0; i < NC_; ++i) {
            const float c = tl[i] * rs;
            const float2 c2 = make_float2(c, c);
            #pragma unroll
            for (int t = 0; t < 5; ++t) yr[i][t] = ffma2(c2, xq[t], yr[i][t]);
        }
    }

    // merge 8 warp partials: warps 0-3 store slabs, warps 4-7 add into them
    if (w < 4) {
        #pragma unroll
        for (int i = 0; i < NC_; ++i)
            #pragma unroll
            for (int t = 0; t < 5; ++t) {
                const int d = 2*lane + 64*t;
                if (d < D_) *(float2*)&slab[w][i][d] = yr[i][t];
            }
    }
    __syncthreads();
    if (w >= 4) {
        #pragma unroll
        for (int i = 0; i < NC_; ++i)
            #pragma unroll
            for (int t = 0; t < 5; ++t) {
                const int d = 2*lane + 64*t;
                if (d < D_) {
                    float2* p = (float2*)&slab[w-4][i][d];
                    float2 v0 = *p;
                    v0.x += yr[i][t].x; v0.y += yr[i][t].y;
                    *p = v0;
                }
            }
    }
    __syncthreads();
    float* yo = g_y + (size_t)b*NC_*D_;
    const float* s0 = &slab[0][0][0];
    const float* s1 = &slab[1][0][0];
    const float* s2 = &slab[2][0][0];
    const float* s3 = &slab[3][0][0];
    for (int idx = threadIdx.x; idx < NC_*D_; idx += 256)
        yo[idx] = (s0[idx] + s1[idx]) + (s2[idx] + s3[idx]);
}

// ---------------------------------------------------------------------------
extern "C" void kernel_launch(void* const* d_in, const int* in_sizes, int n_in,
                              void* d_out, int out_size) {
    const float* x = (const float*)d_in[0];
    const float* W = (const float*)d_in[1];
    if (n_in >= 2 && in_sizes[0] == D_*M_) {    // guard against input-order swap
        x = (const float*)d_in[1];
        W = (const float*)d_in[0];
    }
    float* out = (float*)d_out;

    const int CAPS_SMEM = (D_*64 + 8*304 + 8*64 + 8*64) * (int)sizeof(float);  // ~90.6 KB
    cudaFuncSetAttribute(k_caps, cudaFuncAttributeMaxDynamicSharedMemorySize, CAPS_SMEM);

    // iter 0: c uniform (=0.1) -> y = 0.1*colsum -> o0, v0
    k_colsum<<<dim3(B_, 4), 256>>>(x);
    k_caps<<<dim3(NC_, B_/8), 256, CAPS_SMEM>>>(W, out, 0);
    // iters 1..4: b = x.v -> softmax -> y;  y -> o -> v  (iter 4 writes output)
    for (int it = 1; it <= 4; ++it) {
        k_main<<<B_, 256>>>(x);
        k_caps<<<dim3(NC_, B_/8), 256, CAPS_SMEM>>>(W, out, it == 4 ? 2 : 1);
    }
}

// round 6
// speedup vs baseline: 1.6454x; 1.1208x over previous
#include <cuda_runtime.h>

#define B_  128
#define N_  512
#define D_  300
#define NC_ 10
#define DC_ 64
#define M_  640   // NC_*DC_

// Scratch (device globals; allocation-free per harness rules)
__device__ __align__(16) float g_y0p[B_*4*D_];    // colsum partials [B][4][D]
__device__ __align__(16) float g_v[B_*NC_*D_];    // v = log2e * W_i o_i  [B][NC][D]
__device__ __align__(16) float g_y[B_*NC_*D_];    // y = sum c x          [B][NC][D]
__device__ __align__(16) float g_Wt[M_*D_];       // W transposed [M][D]

// ---- packed f32x2 FMA (PTX-only; ptxas never auto-fuses) -------------------
__device__ __forceinline__ float2 ffma2(float2 a, float2 b, float2 c) {
    float2 d;
    asm("fma.rn.f32x2 %0, %1, %2, %3;"
        : "=l"(*reinterpret_cast<unsigned long long*>(&d))
        : "l"(*reinterpret_cast<const unsigned long long*>(&a)),
          "l"(*reinterpret_cast<const unsigned long long*>(&b)),
          "l"(*reinterpret_cast<const unsigned long long*>(&c)));
    return d;
}

// ---------------------------------------------------------------------------
// Kernel 0: one-time W transpose  Wt[m][d] = W[d][m]
// ---------------------------------------------------------------------------
__global__ void k_transpose(const float* __restrict__ W) {
    __shared__ float t[32][33];
    const int mx = blockIdx.x*32, dy = blockIdx.y*32;
    #pragma unroll
    for (int r = 0; r < 4; ++r) {
        const int d = dy + threadIdx.y + 8*r;
        if (d < D_) t[threadIdx.y + 8*r][threadIdx.x] = W[(size_t)d*M_ + mx + threadIdx.x];
    }
    __syncthreads();
    #pragma unroll
    for (int r = 0; r < 4; ++r) {
        const int m = mx + threadIdx.y + 8*r;
        const int d = dy + threadIdx.x;
        if (d < D_) g_Wt[(size_t)m*D_ + d] = t[threadIdx.x][threadIdx.y + 8*r];
    }
}

// ---------------------------------------------------------------------------
// Kernel 1: per-batch column sums of x (iteration-0 y is 0.1 * colsum)
// ---------------------------------------------------------------------------
__global__ void k_colsum(const float* __restrict__ x) {
    const int b = blockIdx.x, q = blockIdx.y;
    const float* xb = x + (size_t)(b*N_ + q*128)*D_;
    for (int d = threadIdx.x; d < D_; d += blockDim.x) {
        float a0=0.f, a1=0.f, a2=0.f, a3=0.f;
        #pragma unroll 4
        for (int r = 0; r < 128; r += 4) {
            a0 += xb[(size_t)(r+0)*D_ + d];
            a1 += xb[(size_t)(r+1)*D_ + d];
            a2 += xb[(size_t)(r+2)*D_ + d];
            a3 += xb[(size_t)(r+3)*D_ + d];
        }
        g_y0p[(b*4 + q)*D_ + d] = (a0+a1)+(a2+a3);
    }
}

// ---------------------------------------------------------------------------
// Kernel 2 (v3): capsule reduce, NO W in smem (W stays L2-resident).
//   y -> s = W_i^T y -> o = squash(s) -> v = log2e * W_i o
// grid (NC, B/4) = (10,32), 256 threads, b-tile 4, ~10KB smem -> all blocks
// co-resident (~17 warps/SM). S phase reads W (k-coalesced); V phase reads
// Wt (d-coalesced), sharing each Wt load across the 4 batches.
// phase 0: y=0.1*colsum -> v.  phase 1: y=g_y -> v.  phase 2: y=g_y -> out.
// ---------------------------------------------------------------------------
__global__ void __launch_bounds__(256) k_caps(const float* __restrict__ W,
                                              float* __restrict__ out, int phase) {
    __shared__ float ys[4][304];
    __shared__ float sp[4][4][64];   // [h][b][k] S-phase partials
    __shared__ float os[4][64];
    __shared__ float qw[8];
    const int i   = blockIdx.x;
    const int bt  = blockIdx.y*4;
    const int tid = threadIdx.x;

    // load y for 4 batches
    if (phase == 0) {
        #pragma unroll
        for (int bb = 0; bb < 4; ++bb)
            for (int d = tid; d < D_; d += 256) {
                const float* p = g_y0p + (size_t)(bt+bb)*4*D_ + d;
                ys[bb][d] = 0.1f*((p[0] + p[D_]) + (p[2*D_] + p[3*D_]));
            }
    } else {
        #pragma unroll
        for (int bb = 0; bb < 4; ++bb)
            for (int d = tid; d < D_; d += 256)
                ys[bb][d] = g_y[((size_t)(bt+bb)*NC_ + i)*D_ + d];
    }
    __syncthreads();

    // S phase: thread (k = tid&63, h = tid>>6) covers d in [75h, 75h+75),
    // all 4 batches. W[d][i*64+k]: lane-consecutive k -> coalesced L2 hits.
    {
        const int k = tid & 63, h = tid >> 6;
        const float* wp = W + (size_t)(75*h)*M_ + i*DC_ + k;
        float a0=0.f, a1=0.f, a2=0.f, a3=0.f;
        #pragma unroll 5
        for (int dd = 0; dd < 75; ++dd) {
            const float wv = wp[(size_t)dd*M_];
            const int d = 75*h + dd;
            a0 = fmaf(wv, ys[0][d], a0);
            a1 = fmaf(wv, ys[1][d], a1);
            a2 = fmaf(wv, ys[2][d], a2);
            a3 = fmaf(wv, ys[3][d], a3);
        }
        sp[h][0][k] = a0; sp[h][1][k] = a1; sp[h][2][k] = a2; sp[h][3][k] = a3;
    }
    __syncthreads();

    // combine + squash: thread tid -> (b = tid>>6, k = tid&63); 64 k spans 2 warps
    {
        const int b = tid >> 6, k = tid & 63;
        const float s = (sp[0][b][k] + sp[1][b][k]) + (sp[2][b][k] + sp[3][b][k]);
        float q = s*s;
        #pragma unroll
        for (int off = 16; off; off >>= 1) q += __shfl_xor_sync(0xffffffffu, q, off);
        const int w = tid >> 5;
        if ((tid & 31) == 0) qw[w] = q;
        __syncthreads();
        const float ri = rsqrtf(qw[2*b] + qw[2*b+1] + 1e-7f);
        const float o = s * ri;
        os[b][k] = o;
        if (phase == 2) out[((size_t)(bt+b)*NC_ + i)*DC_ + k] = o;
    }
    __syncthreads();

    // V phase: v[b][d] = log2e * sum_k Wt[i*64+k][d] * o[b][k]
    // thread owns d; Wt load shared across 4 batches (1 LDG : 4 FMA).
    if (phase != 2) {
        const float L2E = 1.44269504f;
        for (int d = tid; d < D_; d += 256) {
            const float* wt = g_Wt + (size_t)(i*DC_)*D_ + d;
            float a0=0.f, a1=0.f, a2=0.f, a3=0.f;
            #pragma unroll 8
            for (int k = 0; k < 64; ++k) {
                const float wv = wt[(size_t)k*D_];
                a0 = fmaf(wv, os[0][k], a0);
                a1 = fmaf(wv, os[1][k], a1);
                a2 = fmaf(wv, os[2][k], a2);
                a3 = fmaf(wv, os[3][k], a3);
            }
            g_v[((size_t)(bt+0)*NC_ + i)*D_ + d] = a0 * L2E;
            g_v[((size_t)(bt+1)*NC_ + i)*D_ + d] = a1 * L2E;
            g_v[((size_t)(bt+2)*NC_ + i)*D_ + d] = a2 * L2E;
            g_v[((size_t)(bt+3)*NC_ + i)*D_ + d] = a3 * L2E;
        }
    }
}

// ---------------------------------------------------------------------------
// Kernel 3: main routing pass (one iteration). grid (B), 256 threads.
// Per row j: t_i = x_j . v_i  (v pre-scaled by log2e) -> softmax via exp2
// -> y_i += c_i * x_j.  v/y register-resident; FFMA2; butterfly warp sums.
// ---------------------------------------------------------------------------
__global__ void __launch_bounds__(256, 1) k_main(const float* __restrict__ x) {
    __shared__ __align__(16) float slab[4][NC_][D_];   // 48000 B cross-warp y merge
    const int b    = blockIdx.x;
    const int w    = threadIdx.x >> 5;
    const int lane = threadIdx.x & 31;

    const float* vb = g_v + (size_t)b*NC_*D_;
    float2 vr[NC_][5];
    #pragma unroll
    for (int i = 0; i < NC_; ++i) {
        #pragma unroll
        for (int t = 0; t < 4; ++t)
            vr[i][t] = *(const float2*)(vb + i*D_ + 2*lane + 64*t);
        vr[i][4] = (lane < 22) ? *(const float2*)(vb + i*D_ + 2*lane + 256)
                               : make_float2(0.f, 0.f);
    }
    float2 yr[NC_][5];
    #pragma unroll
    for (int i = 0; i < NC_; ++i)
        #pragma unroll
        for (int t = 0; t < 5; ++t) yr[i][t] = make_float2(0.f, 0.f);

    const float* xb = x + (size_t)b*N_*D_;
    for (int j = w*64; j < w*64 + 64; ++j) {
        const float* xr = xb + (size_t)j*D_;
        float2 xq[5];
        #pragma unroll
        for (int t = 0; t < 4; ++t) xq[t] = *(const float2*)(xr + 2*lane + 64*t);
        xq[4] = (lane < 22) ? *(const float2*)(xr + 2*lane + 256)
                            : make_float2(0.f, 0.f);

        float tl[NC_];
        #pragma unroll
        for (int i = 0; i < NC_; ++i) {
            float2 acc = make_float2(0.f, 0.f);
            #pragma unroll
            for (int t = 0; t < 5; ++t) acc = ffma2(xq[t], vr[i][t], acc);
            tl[i] = acc.x + acc.y;
        }
        // butterfly reduce the 10 dots over 32 lanes (all lanes get full sums)
        #pragma unroll
        for (int i = 0; i < NC_; ++i) {
            #pragma unroll
            for (int off = 16; off; off >>= 1)
                tl[i] += __shfl_xor_sync(0xffffffffu, tl[i], off);
        }
        // softmax over the 10 capsules; v pre-scaled by log2e -> bare exp2
        float se = 0.f;
        #pragma unroll
        for (int i = 0; i < NC_; ++i) { tl[i] = exp2f(tl[i]); se += tl[i]; }
        const float rs = __frcp_rn(se);
        #pragma unroll
        for (int i = 0; i < NC_; ++i) {
            const float c = tl[i] * rs;
            const float2 c2 = make_float2(c, c);
            #pragma unroll
            for (int t = 0; t < 5; ++t) yr[i][t] = ffma2(c2, xq[t], yr[i][t]);
        }
    }

    // merge 8 warp partials: warps 0-3 store slabs, warps 4-7 add into them
    if (w < 4) {
        #pragma unroll
        for (int i = 0; i < NC_; ++i)
            #pragma unroll
            for (int t = 0; t < 5; ++t) {
                const int d = 2*lane + 64*t;
                if (d < D_) *(float2*)&slab[w][i][d] = yr[i][t];
            }
    }
    __syncthreads();
    if (w >= 4) {
        #pragma unroll
        for (int i = 0; i < NC_; ++i)
            #pragma unroll
            for (int t = 0; t < 5; ++t) {
                const int d = 2*lane + 64*t;
                if (d < D_) {
                    float2* p = (float2*)&slab[w-4][i][d];
                    float2 v0 = *p;
                    v0.x += yr[i][t].x; v0.y += yr[i][t].y;
                    *p = v0;
                }
            }
    }
    __syncthreads();
    float* yo = g_y + (size_t)b*NC_*D_;
    const float* s0 = &slab[0][0][0];
    const float* s1 = &slab[1][0][0];
    const float* s2 = &slab[2][0][0];
    const float* s3 = &slab[3][0][0];
    for (int idx = threadIdx.x; idx < NC_*D_; idx += 256)
        yo[idx] = (s0[idx] + s1[idx]) + (s2[idx] + s3[idx]);
}

// ---------------------------------------------------------------------------
extern "C" void kernel_launch(void* const* d_in, const int* in_sizes, int n_in,
                              void* d_out, int out_size) {
    const float* x = (const float*)d_in[0];
    const float* W = (const float*)d_in[1];
    if (n_in >= 2 && in_sizes[0] == D_*M_) {    // guard against input-order swap
        x = (const float*)d_in[1];
        W = (const float*)d_in[0];
    }
    float* out = (float*)d_out;

    k_transpose<<<dim3(M_/32, (D_+31)/32), dim3(32, 8)>>>(W);
    // iter 0: c uniform (=0.1) -> y = 0.1*colsum -> o0, v0
    k_colsum<<<dim3(B_, 4), 256>>>(x);
    k_caps<<<dim3(NC_, B_/4), 256>>>(W, out, 0);
    // iters 1..4: b = x.v -> softmax -> y;  y -> o -> v  (iter 4 writes output)
    for (int it = 1; it <= 4; ++it) {
        k_main<<<B_, 256>>>(x);
        k_caps<<<dim3(NC_, B_/4), 256>>>(W, out, it == 4 ? 2 : 1);
    }
}

// round 7
// speedup vs baseline: 1.7394x; 1.0571x over previous
#include <cuda_runtime.h>

#define B_  128
#define N_  512
#define D_  300
#define NC_ 10
#define DC_ 64
#define M_  640   // NC_*DC_

// Scratch (device globals; allocation-free per harness rules)
__device__ __align__(16) float g_y0p[B_*4*D_];    // colsum partials [B][4][D]
__device__ __align__(16) float g_v[B_*NC_*D_];    // v = log2e * W_i o_i  [B][NC][D]
__device__ __align__(16) float g_y[B_*NC_*D_];    // y = sum c x          [B][NC][D]
__device__ __align__(16) float g_Wt[M_*D_];       // W transposed [M][D]

// ---- packed f32x2 FMA (PTX-only; ptxas never auto-fuses) -------------------
__device__ __forceinline__ float2 ffma2(float2 a, float2 b, float2 c) {
    float2 d;
    asm("fma.rn.f32x2 %0, %1, %2, %3;"
        : "=l"(*reinterpret_cast<unsigned long long*>(&d))
        : "l"(*reinterpret_cast<const unsigned long long*>(&a)),
          "l"(*reinterpret_cast<const unsigned long long*>(&b)),
          "l"(*reinterpret_cast<const unsigned long long*>(&c)));
    return d;
}
// ---- raw MUFU ops (library exp2f/frcp are multi-instr without fast-math) ---
__device__ __forceinline__ float ex2_approx(float x) {
    float r; asm("ex2.approx.f32 %0, %1;" : "=f"(r) : "f"(x)); return r;
}
__device__ __forceinline__ float rcp_approx(float x) {
    float r; asm("rcp.approx.f32 %0, %1;" : "=f"(r) : "f"(x)); return r;
}

// ---------------------------------------------------------------------------
// Kernel 0: one-time W transpose  Wt[m][d] = W[d][m]
// ---------------------------------------------------------------------------
__global__ void k_transpose(const float* __restrict__ W) {
    __shared__ float t[32][33];
    const int mx = blockIdx.x*32, dy = blockIdx.y*32;
    #pragma unroll
    for (int r = 0; r < 4; ++r) {
        const int d = dy + threadIdx.y + 8*r;
        if (d < D_) t[threadIdx.y + 8*r][threadIdx.x] = W[(size_t)d*M_ + mx + threadIdx.x];
    }
    __syncthreads();
    #pragma unroll
    for (int r = 0; r < 4; ++r) {
        const int m = mx + threadIdx.y + 8*r;
        const int d = dy + threadIdx.x;
        if (d < D_) g_Wt[(size_t)m*D_ + d] = t[threadIdx.x][threadIdx.y + 8*r];
    }
}

// ---------------------------------------------------------------------------
// Kernel 1: per-batch column sums of x (iteration-0 y is 0.1 * colsum)
// ---------------------------------------------------------------------------
__global__ void k_colsum(const float* __restrict__ x) {
    const int b = blockIdx.x, q = blockIdx.y;
    const float* xb = x + (size_t)(b*N_ + q*128)*D_;
    for (int d = threadIdx.x; d < D_; d += blockDim.x) {
        float a0=0.f, a1=0.f, a2=0.f, a3=0.f;
        #pragma unroll 4
        for (int r = 0; r < 128; r += 4) {
            a0 += xb[(size_t)(r+0)*D_ + d];
            a1 += xb[(size_t)(r+1)*D_ + d];
            a2 += xb[(size_t)(r+2)*D_ + d];
            a3 += xb[(size_t)(r+3)*D_ + d];
        }
        g_y0p[(b*4 + q)*D_ + d] = (a0+a1)+(a2+a3);
    }
}

// ---------------------------------------------------------------------------
// Kernel 2: capsule reduce, NO W in smem (W stays L2-resident).
//   y -> s = W_i^T y -> o = squash(s) -> v = log2e * W_i o
// grid (NC, B/4) = (10,32), 256 threads, b-tile 4, ~10KB smem.
// phase 0: y=0.1*colsum -> v.  phase 1: y=g_y -> v.  phase 2: y=g_y -> out.
// ---------------------------------------------------------------------------
__global__ void __launch_bounds__(256) k_caps(const float* __restrict__ W,
                                              float* __restrict__ out, int phase) {
    __shared__ float ys[4][304];
    __shared__ float sp[4][4][64];   // [h][b][k] S-phase partials
    __shared__ float os[4][64];
    __shared__ float qw[8];
    const int i   = blockIdx.x;
    const int bt  = blockIdx.y*4;
    const int tid = threadIdx.x;

    if (phase == 0) {
        #pragma unroll
        for (int bb = 0; bb < 4; ++bb)
            for (int d = tid; d < D_; d += 256) {
                const float* p = g_y0p + (size_t)(bt+bb)*4*D_ + d;
                ys[bb][d] = 0.1f*((p[0] + p[D_]) + (p[2*D_] + p[3*D_]));
            }
    } else {
        #pragma unroll
        for (int bb = 0; bb < 4; ++bb)
            for (int d = tid; d < D_; d += 256)
                ys[bb][d] = g_y[((size_t)(bt+bb)*NC_ + i)*D_ + d];
    }
    __syncthreads();

    // S phase: thread (k = tid&63, h = tid>>6) covers d in [75h, 75h+75)
    {
        const int k = tid & 63, h = tid >> 6;
        const float* wp = W + (size_t)(75*h)*M_ + i*DC_ + k;
        float a0=0.f, a1=0.f, a2=0.f, a3=0.f;
        #pragma unroll 5
        for (int dd = 0; dd < 75; ++dd) {
            const float wv = wp[(size_t)dd*M_];
            const int d = 75*h + dd;
            a0 = fmaf(wv, ys[0][d], a0);
            a1 = fmaf(wv, ys[1][d], a1);
            a2 = fmaf(wv, ys[2][d], a2);
            a3 = fmaf(wv, ys[3][d], a3);
        }
        sp[h][0][k] = a0; sp[h][1][k] = a1; sp[h][2][k] = a2; sp[h][3][k] = a3;
    }
    __syncthreads();

    // combine + squash: thread tid -> (b = tid>>6, k = tid&63)
    {
        const int b = tid >> 6, k = tid & 63;
        const float s = (sp[0][b][k] + sp[1][b][k]) + (sp[2][b][k] + sp[3][b][k]);
        float q = s*s;
        #pragma unroll
        for (int off = 16; off; off >>= 1) q += __shfl_xor_sync(0xffffffffu, q, off);
        const int w = tid >> 5;
        if ((tid & 31) == 0) qw[w] = q;
        __syncthreads();
        const float ri = rsqrtf(qw[2*b] + qw[2*b+1] + 1e-7f);
        const float o = s * ri;
        os[b][k] = o;
        if (phase == 2) out[((size_t)(bt+b)*NC_ + i)*DC_ + k] = o;
    }
    __syncthreads();

    // V phase: v[b][d] = log2e * sum_k Wt[i*64+k][d] * o[b][k]
    if (phase != 2) {
        const float L2E = 1.44269504f;
        for (int d = tid; d < D_; d += 256) {
            const float* wt = g_Wt + (size_t)(i*DC_)*D_ + d;
            float a0=0.f, a1=0.f, a2=0.f, a3=0.f;
            #pragma unroll 8
            for (int k = 0; k < 64; ++k) {
                const float wv = wt[(size_t)k*D_];
                a0 = fmaf(wv, os[0][k], a0);
                a1 = fmaf(wv, os[1][k], a1);
                a2 = fmaf(wv, os[2][k], a2);
                a3 = fmaf(wv, os[3][k], a3);
            }
            g_v[((size_t)(bt+0)*NC_ + i)*D_ + d] = a0 * L2E;
            g_v[((size_t)(bt+1)*NC_ + i)*D_ + d] = a1 * L2E;
            g_v[((size_t)(bt+2)*NC_ + i)*D_ + d] = a2 * L2E;
            g_v[((size_t)(bt+3)*NC_ + i)*D_ + d] = a3 * L2E;
        }
    }
}

// ---------------------------------------------------------------------------
// Kernel 3: main routing pass, ILP-2 rows. grid (B), 256 threads.
// Per row j: t_i = x_j . v_i (v pre-scaled by log2e) -> softmax via raw EX2
// -> y_i += c_i * x_j.  v/y register-resident; FFMA2; stage-major butterflies.
// ---------------------------------------------------------------------------
__global__ void __launch_bounds__(256, 1) k_main(const float* __restrict__ x) {
    __shared__ __align__(16) float slab[4][NC_][D_];   // cross-warp y merge
    const int b    = blockIdx.x;
    const int w    = threadIdx.x >> 5;
    const int lane = threadIdx.x & 31;
    const bool tl22 = (lane < 22);

    const float* vb = g_v + (size_t)b*NC_*D_;
    float2 vr[NC_][5];
    #pragma unroll
    for (int i = 0; i < NC_; ++i) {
        #pragma unroll
        for (int t = 0; t < 4; ++t)
            vr[i][t] = *(const float2*)(vb + i*D_ + 2*lane + 64*t);
        vr[i][4] = tl22 ? *(const float2*)(vb + i*D_ + 2*lane + 256)
                        : make_float2(0.f, 0.f);
    }
    float2 yr[NC_][5];
    #pragma unroll
    for (int i = 0; i < NC_; ++i)
        #pragma unroll
        for (int t = 0; t < 5; ++t) yr[i][t] = make_float2(0.f, 0.f);

    const float* xb = x + (size_t)b*N_*D_;
    for (int j = w*64; j < w*64 + 64; j += 2) {
        const float* xrA = xb + (size_t)j*D_;
        const float* xrB = xrA + D_;
        float2 xqA[5], xqB[5];
        #pragma unroll
        for (int t = 0; t < 4; ++t) {
            xqA[t] = *(const float2*)(xrA + 2*lane + 64*t);
            xqB[t] = *(const float2*)(xrB + 2*lane + 64*t);
        }
        xqA[4] = tl22 ? *(const float2*)(xrA + 2*lane + 256) : make_float2(0.f, 0.f);
        xqB[4] = tl22 ? *(const float2*)(xrB + 2*lane + 256) : make_float2(0.f, 0.f);

        float tlA[NC_], tlB[NC_];
        #pragma unroll
        for (int i = 0; i < NC_; ++i) {
            float2 aA = make_float2(0.f, 0.f), aB = make_float2(0.f, 0.f);
            #pragma unroll
            for (int t = 0; t < 5; ++t) {
                aA = ffma2(xqA[t], vr[i][t], aA);
                aB = ffma2(xqB[t], vr[i][t], aB);
            }
            tlA[i] = aA.x + aA.y;
            tlB[i] = aB.x + aB.y;
        }
        // stage-major butterflies: 20 independent chains in flight per stage
        #pragma unroll
        for (int off = 16; off; off >>= 1) {
            #pragma unroll
            for (int i = 0; i < NC_; ++i) {
                tlA[i] += __shfl_xor_sync(0xffffffffu, tlA[i], off);
                tlB[i] += __shfl_xor_sync(0xffffffffu, tlB[i], off);
            }
        }
        // softmax (v carried log2e -> bare EX2); tree-sum denominators
        #pragma unroll
        for (int i = 0; i < NC_; ++i) { tlA[i] = ex2_approx(tlA[i]); tlB[i] = ex2_approx(tlB[i]); }
        float sA = (((tlA[0]+tlA[1])+(tlA[2]+tlA[3]))+((tlA[4]+tlA[5])+(tlA[6]+tlA[7])))+(tlA[8]+tlA[9]);
        float sB = (((tlB[0]+tlB[1])+(tlB[2]+tlB[3]))+((tlB[4]+tlB[5])+(tlB[6]+tlB[7])))+(tlB[8]+tlB[9]);
        const float rA = rcp_approx(sA), rB = rcp_approx(sB);
        #pragma unroll
        for (int i = 0; i < NC_; ++i) {
            const float2 cA = make_float2(tlA[i]*rA, tlA[i]*rA);
            const float2 cB = make_float2(tlB[i]*rB, tlB[i]*rB);
            #pragma unroll
            for (int t = 0; t < 5; ++t)
                yr[i][t] = ffma2(cB, xqB[t], ffma2(cA, xqA[t], yr[i][t]));
        }
    }

    // merge 8 warp partials: warps 0-3 store slabs, warps 4-7 add into them
    if (w < 4) {
        #pragma unroll
        for (int i = 0; i < NC_; ++i)
            #pragma unroll
            for (int t = 0; t < 5; ++t) {
                const int d = 2*lane + 64*t;
                if (d < D_) *(float2*)&slab[w][i][d] = yr[i][t];
            }
    }
    __syncthreads();
    if (w >= 4) {
        #pragma unroll
        for (int i = 0; i < NC_; ++i)
            #pragma unroll
            for (int t = 0; t < 5; ++t) {
                const int d = 2*lane + 64*t;
                if (d < D_) {
                    float2* p = (float2*)&slab[w-4][i][d];
                    float2 v0 = *p;
                    v0.x += yr[i][t].x; v0.y += yr[i][t].y;
                    *p = v0;
                }
            }
    }
    __syncthreads();
    float* yo = g_y + (size_t)b*NC_*D_;
    const float* s0 = &slab[0][0][0];
    const float* s1 = &slab[1][0][0];
    const float* s2 = &slab[2][0][0];
    const float* s3 = &slab[3][0][0];
    for (int idx = threadIdx.x; idx < NC_*D_; idx += 256)
        yo[idx] = (s0[idx] + s1[idx]) + (s2[idx] + s3[idx]);
}

// ---------------------------------------------------------------------------
extern "C" void kernel_launch(void* const* d_in, const int* in_sizes, int n_in,
                              void* d_out, int out_size) {
    const float* x = (const float*)d_in[0];
    const float* W = (const float*)d_in[1];
    if (n_in >= 2 && in_sizes[0] == D_*M_) {    // guard against input-order swap
        x = (const float*)d_in[1];
        W = (const float*)d_in[0];
    }
    float* out = (float*)d_out;

    k_transpose<<<dim3(M_/32, (D_+31)/32), dim3(32, 8)>>>(W);
    // iter 0: c uniform (=0.1) -> y = 0.1*colsum -> o0, v0
    k_colsum<<<dim3(B_, 4), 256>>>(x);
    k_caps<<<dim3(NC_, B_/4), 256>>>(W, out, 0);
    // iters 1..4: b = x.v -> softmax -> y;  y -> o -> v  (iter 4 writes output)
    for (int it = 1; it <= 4; ++it) {
        k_main<<<B_, 256>>>(x);
        k_caps<<<dim3(NC_, B_/4), 256>>>(W, out, it == 4 ? 2 : 1);
    }
}